// round 1
// baseline (speedup 1.0000x reference)
#include <cuda_runtime.h>
#include <cuda_bf16.h>
#include <math.h>
#include <stdint.h>

#define M_ROWS 8192
#define C_COLS 4096
#define D_DIM  768

#define BM 64
#define BN 64
#define BK 64
#define NTHREADS 256

#define A_LD (D_DIM + 8)                 // 776 bf16 elems per smem A row (pad: stride%32words==4)
#define B_LD (BK + 8)                    // 72 bf16 elems per smem B row
#define SMEM_A_ELEMS (BM * A_LD)         // 49664
#define SMEM_B_ELEMS (2 * BN * B_LD)     // 9216 (double buffered)
#define SMEM_BYTES ((SMEM_A_ELEMS + SMEM_B_ELEMS) * 2)  // 117760 B

// Scratch (device globals are the sanctioned no-alloc workaround)
__device__ __align__(16) __nv_bfloat16 g_A[M_ROWS * D_DIM];
__device__ __align__(16) __nv_bfloat16 g_B[C_COLS * D_DIM];
__device__ float g_at[M_ROWS];
__device__ float g_bt[C_COLS];

__device__ __forceinline__ void cp16(uint32_t dst, const void* src) {
    asm volatile("cp.async.cg.shared.global [%0], [%1], 16;" :: "r"(dst), "l"(src));
}
__device__ __forceinline__ void cp_commit() { asm volatile("cp.async.commit_group;"); }
template<int N>
__device__ __forceinline__ void cp_wait() { asm volatile("cp.async.wait_group %0;" :: "n"(N)); }

// ---------------------------------------------------------------------------
// Preprocess: scale -> exp_map0 -> store bf16 space components + fp32 time.
// One block (256 thr) per row, 768 = 3*256 elements.
// ---------------------------------------------------------------------------
__global__ void prep_kernel(const float* __restrict__ x,
                            const float* __restrict__ curv_log,
                            const float* __restrict__ alpha_log,
                            int which) {
    const int row = blockIdx.x;
    const int tid = threadIdx.x;
    const float alpha = expf(alpha_log[0]);
    const float curv  = expf(curv_log[0]);
    const float* xr = x + (size_t)row * D_DIM;

    float v0 = xr[tid      ] * alpha;
    float v1 = xr[tid + 256] * alpha;
    float v2 = xr[tid + 512] * alpha;
    float ss = v0 * v0 + v1 * v1 + v2 * v2;
    #pragma unroll
    for (int o = 16; o > 0; o >>= 1) ss += __shfl_xor_sync(0xffffffffu, ss, o);
    __shared__ float ws[8];
    if ((tid & 31) == 0) ws[tid >> 5] = ss;
    __syncthreads();
    const float sumsq = ws[0] + ws[1] + ws[2] + ws[3] + ws[4] + ws[5] + ws[6] + ws[7];

    const float rc = sqrtf(curv) * sqrtf(sumsq);
    const float sf = sinhf(rc) / fmaxf(rc, 1e-8f);

    __nv_bfloat16* out = which ? g_B : g_A;
    out[(size_t)row * D_DIM + tid      ] = __float2bfloat16(sf * v0);
    out[(size_t)row * D_DIM + tid + 256] = __float2bfloat16(sf * v1);
    out[(size_t)row * D_DIM + tid + 512] = __float2bfloat16(sf * v2);
    if (tid == 0) {
        float* tout = which ? g_bt : g_at;
        tout[row] = sqrtf(1.0f / curv + sf * sf * sumsq);
    }
}

// ---------------------------------------------------------------------------
// Main: per block = 64 rows x all 4096 cols. A panel resident in SMEM,
// B double-buffered via cp.async. bf16 mma.sync m16n8k16. Track top-2
// smallest v = x_time*y_time - dot (monotone with dist) + positive v.
// ---------------------------------------------------------------------------
__device__ __forceinline__ void load_b_chunk(__nv_bfloat16* sB, int tid,
                                             int ct, int kc, int buf) {
    const __nv_bfloat16* Bg = g_B + (size_t)(ct * BN) * D_DIM + kc * BK;
    #pragma unroll
    for (int t = 0; t < 2; ++t) {
        int i  = tid + t * NTHREADS;   // 0..511 ; 64 cols x 8 chunks of 16B
        int cc = i >> 3;
        int kk = (i & 7) * 8;
        uint32_t dst = (uint32_t)__cvta_generic_to_shared(sB + buf * (BN * B_LD) + cc * B_LD + kk);
        cp16(dst, Bg + (size_t)cc * D_DIM + kk);
    }
}

__global__ void __launch_bounds__(NTHREADS, 1)
clloss_main(const int* __restrict__ target,
            const float* __restrict__ curv_log,
            float* __restrict__ out) {
    extern __shared__ __nv_bfloat16 smem[];
    __nv_bfloat16* sA = smem;
    __nv_bfloat16* sB = smem + SMEM_A_ELEMS;

    const int tid  = threadIdx.x;
    const int warp = tid >> 5;
    const int lane = tid & 31;
    const int g    = lane >> 2;   // 0..7
    const int q    = lane & 3;    // 0..3
    const int wm   = warp >> 2;   // 0..1 (m tile)
    const int wn   = warp & 3;    // 0..3 (n tile)
    const int brow = blockIdx.x * BM;

    // Issue resident A panel load (once)
    {
        const __nv_bfloat16* Ag = g_A + (size_t)brow * D_DIM;
        #pragma unroll
        for (int t = 0; t < (BM * D_DIM / 8) / NTHREADS; ++t) {  // 24 iters
            int i = tid + t * NTHREADS;
            int r = i / (D_DIM / 8);
            int c = (i % (D_DIM / 8)) * 8;
            uint32_t dst = (uint32_t)__cvta_generic_to_shared(sA + r * A_LD + c);
            cp16(dst, Ag + (size_t)r * D_DIM + c);
        }
        cp_commit();
    }

    // Per-thread row metadata (4 rows: wm*32 + {g, g+8, g+16, g+24})
    float xt[4]; int tg[4];
    #pragma unroll
    for (int i = 0; i < 4; ++i) {
        int rl = wm * 32 + (i >> 1) * 16 + (i & 1) * 8 + g;
        xt[i] = g_at[brow + rl];
        tg[i] = target[brow + rl];
    }
    const float FINF = __int_as_float(0x7f800000);
    float m1[4], m2[4], vpos[4];
    #pragma unroll
    for (int i = 0; i < 4; ++i) { m1[i] = FINF; m2[i] = FINF; vpos[i] = FINF; }

    load_b_chunk(sB, tid, 0, 0, 0);
    cp_commit();

    const int NCT = C_COLS / BN;  // 64
    const int NKC = D_DIM / BK;   // 12

    for (int ct = 0; ct < NCT; ++ct) {
        float acc[2][2][4];
        #pragma unroll
        for (int mi = 0; mi < 2; ++mi)
            #pragma unroll
            for (int ni = 0; ni < 2; ++ni)
                #pragma unroll
                for (int r = 0; r < 4; ++r) acc[mi][ni][r] = 0.0f;

        for (int kc = 0; kc < NKC; ++kc) {
            if (kc + 1 < NKC)      load_b_chunk(sB, tid, ct, kc + 1, (kc + 1) & 1);
            else if (ct + 1 < NCT) load_b_chunk(sB, tid, ct + 1, 0, 0);
            cp_commit();
            cp_wait<1>();
            __syncthreads();

            const __nv_bfloat16* sBb = sB + (kc & 1) * (BN * B_LD);
            #pragma unroll
            for (int ks = 0; ks < BK / 16; ++ks) {
                const int kA = kc * BK + ks * 16;
                uint32_t a[2][4];
                #pragma unroll
                for (int mi = 0; mi < 2; ++mi) {
                    const __nv_bfloat16* p = sA + (wm * 32 + mi * 16 + g) * A_LD + kA + 2 * q;
                    a[mi][0] = *(const uint32_t*)(p);
                    a[mi][1] = *(const uint32_t*)(p + 8 * A_LD);
                    a[mi][2] = *(const uint32_t*)(p + 8);
                    a[mi][3] = *(const uint32_t*)(p + 8 * A_LD + 8);
                }
                uint32_t b[2][2];
                #pragma unroll
                for (int ni = 0; ni < 2; ++ni) {
                    const __nv_bfloat16* p = sBb + (wn * 16 + ni * 8 + g) * B_LD + ks * 16 + 2 * q;
                    b[ni][0] = *(const uint32_t*)(p);
                    b[ni][1] = *(const uint32_t*)(p + 8);
                }
                #pragma unroll
                for (int mi = 0; mi < 2; ++mi)
                    #pragma unroll
                    for (int ni = 0; ni < 2; ++ni)
                        asm volatile(
                            "mma.sync.aligned.m16n8k16.row.col.f32.bf16.bf16.f32 "
                            "{%0,%1,%2,%3}, {%4,%5,%6,%7}, {%8,%9}, {%0,%1,%2,%3};\n"
                            : "+f"(acc[mi][ni][0]), "+f"(acc[mi][ni][1]),
                              "+f"(acc[mi][ni][2]), "+f"(acc[mi][ni][3])
                            : "r"(a[mi][0]), "r"(a[mi][1]), "r"(a[mi][2]), "r"(a[mi][3]),
                              "r"(b[ni][0]), "r"(b[ni][1]));
            }
            __syncthreads();
        }

        // Epilogue: v = xt*yt - dot ; track top-2 smallest (excl. positive) + positive
        #pragma unroll
        for (int ni = 0; ni < 2; ++ni) {
            const int cg  = ct * BN + wn * 16 + ni * 8 + 2 * q;
            const float yt0 = g_bt[cg];
            const float yt1 = g_bt[cg + 1];
            #pragma unroll
            for (int mi = 0; mi < 2; ++mi) {
                #pragma unroll
                for (int h = 0; h < 2; ++h) {
                    const int i = mi * 2 + h;
                    const float va = fmaf(xt[i], yt0, -acc[mi][ni][h * 2 + 0]);
                    const float vb = fmaf(xt[i], yt1, -acc[mi][ni][h * 2 + 1]);
                    if (cg == tg[i]) vpos[i] = va;
                    else if (va < m1[i]) { m2[i] = m1[i]; m1[i] = va; }
                    else if (va < m2[i]) { m2[i] = va; }
                    if (cg + 1 == tg[i]) vpos[i] = vb;
                    else if (vb < m1[i]) { m2[i] = m1[i]; m1[i] = vb; }
                    else if (vb < m2[i]) { m2[i] = vb; }
                }
            }
        }
    }

    // Quad merge (lanes sharing rows: same g, q=0..3) via shfl
    #pragma unroll
    for (int i = 0; i < 4; ++i) {
        #pragma unroll
        for (int off = 1; off <= 2; off <<= 1) {
            float o1 = __shfl_xor_sync(0xffffffffu, m1[i], off);
            float o2 = __shfl_xor_sync(0xffffffffu, m2[i], off);
            float op = __shfl_xor_sync(0xffffffffu, vpos[i], off);
            float n1 = fminf(m1[i], o1);
            float n2 = fminf(fmaxf(m1[i], o1), fminf(m2[i], o2));
            m1[i] = n1; m2[i] = n2;
            vpos[i] = fminf(vpos[i], op);
        }
    }

    __shared__ float r1[4][BM], r2[4][BM], rp[4][BM];
    if (q == 0) {
        #pragma unroll
        for (int i = 0; i < 4; ++i) {
            int rl = wm * 32 + (i >> 1) * 16 + (i & 1) * 8 + g;
            r1[wn][rl] = m1[i]; r2[wn][rl] = m2[i]; rp[wn][rl] = vpos[i];
        }
    }
    __syncthreads();

    if (tid < BM) {
        float a1 = r1[0][tid], a2 = r2[0][tid], ap = rp[0][tid];
        #pragma unroll
        for (int w = 1; w < 4; ++w) {
            float o1 = r1[w][tid], o2 = r2[w][tid];
            float n1 = fminf(a1, o1);
            a2 = fminf(fmaxf(a1, o1), fminf(a2, o2));
            a1 = n1;
            ap = fminf(ap, rp[w][tid]);
        }
        const float curv  = expf(curv_log[0]);
        const float sc    = sqrtf(curv);
        const float clamp = 1.0f + 1e-8f;  // folds to 1.0f in fp32 — matches reference
        const float dp = acoshf(fmaxf(curv * ap, clamp)) / sc;
        const float d1 = acoshf(fmaxf(curv * a1, clamp)) / sc;
        const float d2 = acoshf(fmaxf(curv * a2, clamp)) / sc;
        // scores = -dist / CL_TEMP, CL_TEMP = 1
        const float s0 = -dp, s1 = -d1, s2 = -d2;
        const float mx = fmaxf(s0, fmaxf(s1, s2));
        const float loss = mx + logf(expf(s0 - mx) + expf(s1 - mx) + expf(s2 - mx)) - s0;
        out[brow + tid] = loss;
    }
}

// ---------------------------------------------------------------------------
extern "C" void kernel_launch(void* const* d_in, const int* in_sizes, int n_in,
                              void* d_out, int out_size) {
    const float* text      = (const float*)d_in[0];
    const float* label     = (const float*)d_in[1];
    const int*   tgt       = (const int*)d_in[2];
    const float* curv_log  = (const float*)d_in[3];
    const float* ta_log    = (const float*)d_in[4];
    const float* la_log    = (const float*)d_in[5];
    float* out = (float*)d_out;

    cudaFuncSetAttribute(clloss_main, cudaFuncAttributeMaxDynamicSharedMemorySize, SMEM_BYTES);

    prep_kernel<<<M_ROWS, 256>>>(text,  curv_log, ta_log, 0);
    prep_kernel<<<C_COLS, 256>>>(label, curv_log, la_log, 1);
    clloss_main<<<M_ROWS / BM, NTHREADS, SMEM_BYTES>>>(tgt, curv_log, out);
}

// round 3
// speedup vs baseline: 1.1837x; 1.1837x over previous
#include <cuda_runtime.h>
#include <cuda_bf16.h>
#include <math.h>
#include <stdint.h>

#define M_ROWS 8192
#define C_COLS 4096
#define D_DIM  768

#define BM 64
#define BN 128
#define BK 64
#define NTH 256

#define A_LD (D_DIM + 8)      // 776 bf16 (row stride 1552B; mod128 = 16 -> ldmatrix conflict-free)
#define B_LD (BK + 8)         // 72 bf16  (row stride 144B;  mod128 = 16 -> conflict-free)
#define ASZ  (BM * A_LD)      // 49664 elems
#define BSTG (BN * B_LD)      // 9216 elems per stage
#define SBT_ELEMS C_COLS
#define SMEM_BYTES ((ASZ + 2 * BSTG) * 2 + SBT_ELEMS * 4)   // 99328+36864+16384 = 152576

#define NCT (C_COLS / BN)     // 32
#define NKC (D_DIM / BK)      // 12
#define NSTG (NCT * NKC)      // 384

__device__ __align__(16) __nv_bfloat16 g_A[M_ROWS * D_DIM];
__device__ __align__(16) __nv_bfloat16 g_B[C_COLS * D_DIM];
__device__ float g_at[M_ROWS];
__device__ float g_bt[C_COLS];

__device__ __forceinline__ uint32_t smem_u32(const void* p) {
    uint32_t a;
    asm("{ .reg .u64 t; cvta.to.shared.u64 t, %1; cvt.u32.u64 %0, t; }" : "=r"(a) : "l"(p));
    return a;
}
__device__ __forceinline__ void cp16(uint32_t dst, const void* src) {
    asm volatile("cp.async.cg.shared.global [%0], [%1], 16;" :: "r"(dst), "l"(src));
}
__device__ __forceinline__ void cp_commit() { asm volatile("cp.async.commit_group;"); }
template<int N> __device__ __forceinline__ void cp_wait() {
    asm volatile("cp.async.wait_group %0;" :: "n"(N));
}
__device__ __forceinline__ void ldsm4(uint32_t* r, uint32_t addr) {
    asm volatile("ldmatrix.sync.aligned.m8n8.x4.shared.b16 {%0,%1,%2,%3}, [%4];"
                 : "=r"(r[0]), "=r"(r[1]), "=r"(r[2]), "=r"(r[3]) : "r"(addr));
}
__device__ __forceinline__ void mma16816(float* c, const uint32_t* a, uint32_t b0, uint32_t b1) {
    asm volatile(
        "mma.sync.aligned.m16n8k16.row.col.f32.bf16.bf16.f32 "
        "{%0,%1,%2,%3}, {%4,%5,%6,%7}, {%8,%9}, {%0,%1,%2,%3};\n"
        : "+f"(c[0]), "+f"(c[1]), "+f"(c[2]), "+f"(c[3])
        : "r"(a[0]), "r"(a[1]), "r"(a[2]), "r"(a[3]), "r"(b0), "r"(b1));
}

// ---------------------------------------------------------------------------
// Prep: scale -> exp_map0 -> bf16 space comps + fp32 time. One block per row.
// ---------------------------------------------------------------------------
__global__ void prep_kernel(const float* __restrict__ text,
                            const float* __restrict__ label,
                            const float* __restrict__ curv_log,
                            const float* __restrict__ ta_log,
                            const float* __restrict__ la_log) {
    const int which = blockIdx.x >= M_ROWS;
    const int row = which ? blockIdx.x - M_ROWS : blockIdx.x;
    const int tid = threadIdx.x;
    const float alpha = expf(which ? la_log[0] : ta_log[0]);
    const float curv  = expf(curv_log[0]);
    const float* xr = (which ? label : text) + (size_t)row * D_DIM;

    float v0 = xr[tid      ] * alpha;
    float v1 = xr[tid + 256] * alpha;
    float v2 = xr[tid + 512] * alpha;
    float ss = v0 * v0 + v1 * v1 + v2 * v2;
    #pragma unroll
    for (int o = 16; o > 0; o >>= 1) ss += __shfl_xor_sync(0xffffffffu, ss, o);
    __shared__ float ws[8];
    if ((tid & 31) == 0) ws[tid >> 5] = ss;
    __syncthreads();
    const float sumsq = ws[0]+ws[1]+ws[2]+ws[3]+ws[4]+ws[5]+ws[6]+ws[7];

    const float rc = sqrtf(curv) * sqrtf(sumsq);
    const float sf = sinhf(rc) / fmaxf(rc, 1e-8f);

    __nv_bfloat16* out = which ? g_B : g_A;
    out[(size_t)row * D_DIM + tid      ] = __float2bfloat16(sf * v0);
    out[(size_t)row * D_DIM + tid + 256] = __float2bfloat16(sf * v1);
    out[(size_t)row * D_DIM + tid + 512] = __float2bfloat16(sf * v2);
    if (tid == 0)
        (which ? g_bt : g_at)[row] = sqrtf(1.0f / curv + sf * sf * sumsq);
}

// ---------------------------------------------------------------------------
// Main GEMM + fused top-2 tracking. grid = 128 blocks (M/64), 256 threads.
// A panel (64x768) resident in smem; B streamed in 128x64 double-buffered
// stages via cp.async; fragments via ldmatrix.x4; one syncthreads per stage.
// ---------------------------------------------------------------------------
__device__ __forceinline__ void load_b_stage(__nv_bfloat16* sB, int idx, int buf, int tid) {
    const int ct = idx / NKC, kc = idx - ct * NKC;
    const __nv_bfloat16* Bg = g_B + (size_t)(ct * BN) * D_DIM + kc * BK;
    __nv_bfloat16* dst = sB + buf * BSTG;
    #pragma unroll
    for (int t = 0; t < 4; ++t) {              // 1024 cp16s total
        int i = tid + t * NTH;
        int r = i >> 3, ch = (i & 7) * 8;
        cp16(smem_u32(dst + r * B_LD + ch), Bg + (size_t)r * D_DIM + ch);
    }
}

__global__ void __launch_bounds__(NTH, 1)
clloss_main(const int* __restrict__ target,
            const float* __restrict__ curv_log,
            float* __restrict__ out) {
    extern __shared__ __nv_bfloat16 smem[];
    __nv_bfloat16* sA = smem;
    __nv_bfloat16* sB = smem + ASZ;
    float* sbt = (float*)(smem + ASZ + 2 * BSTG);

    const int tid  = threadIdx.x;
    const int warp = tid >> 5;
    const int lane = tid & 31;
    const int g    = lane >> 2;    // 0..7
    const int q    = lane & 3;     // 0..3
    const int wm   = warp >> 2;    // 0..1
    const int wn   = warp & 3;     // 0..3
    const int brow = blockIdx.x * BM;

    // Prologue: resident A panel + sbt + first B stage.
    {
        const __nv_bfloat16* Ag = g_A + (size_t)brow * D_DIM;
        #pragma unroll
        for (int t = 0; t < 24; ++t) {         // 6144 cp16s
            int i = tid + t * NTH;
            int r = i / (D_DIM / 8);
            int c = (i % (D_DIM / 8)) * 8;
            cp16(smem_u32(sA + r * A_LD + c), Ag + (size_t)r * D_DIM + c);
        }
        #pragma unroll
        for (int i = tid; i < C_COLS; i += NTH) sbt[i] = g_bt[i];
        load_b_stage(sB, 0, 0, tid);
        cp_commit();
    }

    // ldmatrix lane addressing (precomputed, byte offsets in shared space)
    const uint32_t sA_u = smem_u32(sA);
    const uint32_t sB_u = smem_u32(sB);
    const uint32_t aAddr0 = sA_u + (uint32_t)(((wm * 32 + (lane & 15)) * A_LD + (lane >> 4) * 8) * 2);
    const uint32_t aAddr1 = aAddr0 + 16 * A_LD * 2;
    const int bn  = (lane & 7) + ((lane & 16) >> 1);       // n-row within 16
    const uint32_t bOffLane = (uint32_t)(((wn * 32 + bn) * B_LD + ((lane >> 3) & 1) * 8) * 2);

    // Per-thread row metadata (rows wm*32 + mi*16 + h*8 + g)
    float xt[4]; int tg[4];
    #pragma unroll
    for (int i = 0; i < 4; ++i) {
        int rl = wm * 32 + (i >> 1) * 16 + (i & 1) * 8 + g;
        xt[i] = g_at[brow + rl];
        tg[i] = target[brow + rl];
    }
    const float FINF = __int_as_float(0x7f800000);
    float m1 = FINF, m2 = FINF, vp = FINF;

    int idx = 0;
    for (int ct = 0; ct < NCT; ++ct) {
        float acc[2][4][4];
        #pragma unroll
        for (int mi = 0; mi < 2; ++mi)
            #pragma unroll
            for (int ni = 0; ni < 4; ++ni)
                #pragma unroll
                for (int r = 0; r < 4; ++r) acc[mi][ni][r] = 0.0f;

        for (int kc = 0; kc < NKC; ++kc, ++idx) {
            cp_wait<0>();
            __syncthreads();            // stage idx visible; all done reading buf (idx+1)&1
            if (idx + 1 < NSTG) {
                load_b_stage(sB, idx + 1, (idx + 1) & 1, tid);
                cp_commit();
            }
            const uint32_t bBase = sB_u + (uint32_t)((idx & 1) * BSTG * 2) + bOffLane;
            #pragma unroll
            for (int ks = 0; ks < 4; ++ks) {
                const int kA = kc * BK + ks * 16;
                uint32_t a[2][4], b[2][4];
                ldsm4(a[0], aAddr0 + kA * 2);
                ldsm4(a[1], aAddr1 + kA * 2);
                ldsm4(b[0], bBase + ks * 32);
                ldsm4(b[1], bBase + ks * 32 + 16 * B_LD * 2);
                #pragma unroll
                for (int mi = 0; mi < 2; ++mi)
                    #pragma unroll
                    for (int ni = 0; ni < 4; ++ni)
                        mma16816(acc[mi][ni], a[mi],
                                 b[ni >> 1][(ni & 1) * 2], b[ni >> 1][(ni & 1) * 2 + 1]);
            }
        }

        // Fused epilogue on register fragments: v = xt*yt - dot (monotone in dist)
        #pragma unroll
        for (int ni = 0; ni < 4; ++ni) {
            const int cg  = ct * BN + wn * 32 + ni * 8 + 2 * q;
            const float yt0 = sbt[cg];
            const float yt1 = sbt[cg + 1];
            #pragma unroll
            for (int mi = 0; mi < 2; ++mi) {
                #pragma unroll
                for (int h = 0; h < 2; ++h) {
                    const int i = mi * 2 + h;
                    const float va = fmaf(xt[i], yt0, -acc[mi][ni][h * 2 + 0]);
                    const float vb = fmaf(xt[i], yt1, -acc[mi][ni][h * 2 + 1]);
                    if (cg == tg[i]) vp = (i == mi * 2 + h) ? va : vp;  // placeholder folded below
                    // (rewritten explicitly below for clarity)
                }
            }
        }
        // NOTE: the loop above is replaced by the exact tracking loop:
        #pragma unroll
        for (int ni = 0; ni < 4; ++ni) {
            const int cg  = ct * BN + wn * 32 + ni * 8 + 2 * q;
            (void)cg;
        }
        idx = idx;  // no-op
        // real tracking (kept single copy):
        #pragma unroll
        for (int ni = 0; ni < 4; ++ni) {
            const int cg  = ct * BN + wn * 32 + ni * 8 + 2 * q;
            const float yt0 = sbt[cg];
            const float yt1 = sbt[cg + 1];
            #pragma unroll
            for (int mi = 0; mi < 2; ++mi) {
                #pragma unroll
                for (int h = 0; h < 2; ++h) {
                    const int i = mi * 2 + h;
                    const float va = fmaf(xt[i], yt0, -acc[mi][ni][h * 2 + 0]);
                    const float vb = fmaf(xt[i], yt1, -acc[mi][ni][h * 2 + 1]);
                    // tracked per-row slots: fold via helper arrays below
                    if (i == 0) {
                        if (cg == tg[0]) vp = va; else if (va < m1) { m2 = m1; m1 = va; } else if (va < m2) m2 = va;
                        if (cg + 1 == tg[0]) vp = vb; else if (vb < m1) { m2 = m1; m1 = vb; } else if (vb < m2) m2 = vb;
                    }
                }
            }
        }
    }

    // ----- the above epilogue was wrong-structured; do the full correct pass -----
    // (dead stores above are removed by recomputation below is impossible; so this
    //  kernel version tracks per-row extrema in arrays instead:)
    out[0] = out[0];  // unreachable-safe no-op
}

// ===========================================================================
// The kernel above contains a structural mistake in the epilogue; use this
// corrected definition instead (same name via macro is not possible), so the
// real kernel is defined here and used by kernel_launch.
// ===========================================================================
__global__ void __launch_bounds__(NTH, 1)
clloss_main2(const int* __restrict__ target,
             const float* __restrict__ curv_log,
             float* __restrict__ out) {
    extern __shared__ __nv_bfloat16 smem[];
    __nv_bfloat16* sA = smem;
    __nv_bfloat16* sB = smem + ASZ;
    float* sbt = (float*)(smem + ASZ + 2 * BSTG);

    const int tid  = threadIdx.x;
    const int warp = tid >> 5;
    const int lane = tid & 31;
    const int g    = lane >> 2;
    const int q    = lane & 3;
    const int wm   = warp >> 2;
    const int wn   = warp & 3;
    const int brow = blockIdx.x * BM;

    {
        const __nv_bfloat16* Ag = g_A + (size_t)brow * D_DIM;
        #pragma unroll
        for (int t = 0; t < 24; ++t) {
            int i = tid + t * NTH;
            int r = i / (D_DIM / 8);
            int c = (i % (D_DIM / 8)) * 8;
            cp16(smem_u32(sA + r * A_LD + c), Ag + (size_t)r * D_DIM + c);
        }
        #pragma unroll
        for (int i = tid; i < C_COLS; i += NTH) sbt[i] = g_bt[i];
        load_b_stage(sB, 0, 0, tid);
        cp_commit();
    }

    const uint32_t sA_u = smem_u32(sA);
    const uint32_t sB_u = smem_u32(sB);
    const uint32_t aAddr0 = sA_u + (uint32_t)(((wm * 32 + (lane & 15)) * A_LD + (lane >> 4) * 8) * 2);
    const uint32_t aAddr1 = aAddr0 + 16 * A_LD * 2;
    const int bn  = (lane & 7) + ((lane & 16) >> 1);
    const uint32_t bOffLane = (uint32_t)(((wn * 32 + bn) * B_LD + ((lane >> 3) & 1) * 8) * 2);

    float xt[4]; int tg[4];
    #pragma unroll
    for (int i = 0; i < 4; ++i) {
        int rl = wm * 32 + (i >> 1) * 16 + (i & 1) * 8 + g;
        xt[i] = g_at[brow + rl];
        tg[i] = target[brow + rl];
    }
    const float FINF = __int_as_float(0x7f800000);
    float m1[4], m2[4], vp[4];
    #pragma unroll
    for (int i = 0; i < 4; ++i) { m1[i] = FINF; m2[i] = FINF; vp[i] = FINF; }

    int idx = 0;
    for (int ct = 0; ct < NCT; ++ct) {
        float acc[2][4][4];
        #pragma unroll
        for (int mi = 0; mi < 2; ++mi)
            #pragma unroll
            for (int ni = 0; ni < 4; ++ni)
                #pragma unroll
                for (int r = 0; r < 4; ++r) acc[mi][ni][r] = 0.0f;

        for (int kc = 0; kc < NKC; ++kc, ++idx) {
            cp_wait<0>();
            __syncthreads();
            if (idx + 1 < NSTG) {
                load_b_stage(sB, idx + 1, (idx + 1) & 1, tid);
                cp_commit();
            }
            const uint32_t bBase = sB_u + (uint32_t)((idx & 1) * BSTG * 2) + bOffLane;
            #pragma unroll
            for (int ks = 0; ks < 4; ++ks) {
                const int kA = kc * BK + ks * 16;
                uint32_t a[2][4], b[2][4];
                ldsm4(a[0], aAddr0 + kA * 2);
                ldsm4(a[1], aAddr1 + kA * 2);
                ldsm4(b[0], bBase + ks * 32);
                ldsm4(b[1], bBase + ks * 32 + 16 * B_LD * 2);
                #pragma unroll
                for (int mi = 0; mi < 2; ++mi)
                    #pragma unroll
                    for (int ni = 0; ni < 4; ++ni)
                        mma16816(acc[mi][ni], a[mi],
                                 b[ni >> 1][(ni & 1) * 2], b[ni >> 1][(ni & 1) * 2 + 1]);
            }
        }

        #pragma unroll
        for (int ni = 0; ni < 4; ++ni) {
            const int cg  = ct * BN + wn * 32 + ni * 8 + 2 * q;
            const float yt0 = sbt[cg];
            const float yt1 = sbt[cg + 1];
            #pragma unroll
            for (int mi = 0; mi < 2; ++mi) {
                #pragma unroll
                for (int h = 0; h < 2; ++h) {
                    const int i = mi * 2 + h;
                    const float va = fmaf(xt[i], yt0, -acc[mi][ni][h * 2 + 0]);
                    const float vb = fmaf(xt[i], yt1, -acc[mi][ni][h * 2 + 1]);
                    if (cg == tg[i]) vp[i] = va;
                    else if (va < m1[i]) { m2[i] = m1[i]; m1[i] = va; }
                    else if (va < m2[i]) m2[i] = va;
                    if (cg + 1 == tg[i]) vp[i] = vb;
                    else if (vb < m1[i]) { m2[i] = m1[i]; m1[i] = vb; }
                    else if (vb < m2[i]) m2[i] = vb;
                }
            }
        }
    }

    // Quad merge (q=0..3 share rows)
    #pragma unroll
    for (int i = 0; i < 4; ++i) {
        #pragma unroll
        for (int off = 1; off <= 2; off <<= 1) {
            float o1 = __shfl_xor_sync(0xffffffffu, m1[i], off);
            float o2 = __shfl_xor_sync(0xffffffffu, m2[i], off);
            float op = __shfl_xor_sync(0xffffffffu, vp[i], off);
            float n1 = fminf(m1[i], o1);
            float n2 = fminf(fmaxf(m1[i], o1), fminf(m2[i], o2));
            m1[i] = n1; m2[i] = n2;
            vp[i] = fminf(vp[i], op);
        }
    }

    __shared__ float r1[4][BM], r2[4][BM], rp[4][BM];
    if (q == 0) {
        #pragma unroll
        for (int i = 0; i < 4; ++i) {
            int rl = wm * 32 + (i >> 1) * 16 + (i & 1) * 8 + g;
            r1[wn][rl] = m1[i]; r2[wn][rl] = m2[i]; rp[wn][rl] = vp[i];
        }
    }
    __syncthreads();

    if (tid < BM) {
        float a1 = r1[0][tid], a2 = r2[0][tid], ap = rp[0][tid];
        #pragma unroll
        for (int w = 1; w < 4; ++w) {
            float o1 = r1[w][tid], o2 = r2[w][tid];
            float n1 = fminf(a1, o1);
            a2 = fminf(fmaxf(a1, o1), fminf(a2, o2));
            a1 = n1;
            ap = fminf(ap, rp[w][tid]);
        }
        const float curv = expf(curv_log[0]);
        const float sc = sqrtf(curv);
        const float dp = acoshf(fmaxf(curv * ap, 1.0f)) / sc;
        const float d1 = acoshf(fmaxf(curv * a1, 1.0f)) / sc;
        const float d2 = acoshf(fmaxf(curv * a2, 1.0f)) / sc;
        const float s0 = -dp, s1 = -d1, s2 = -d2;
        const float mx = fmaxf(s0, fmaxf(s1, s2));
        out[brow + tid] = mx + logf(expf(s0 - mx) + expf(s1 - mx) + expf(s2 - mx)) - s0;
    }
}

extern "C" void kernel_launch(void* const* d_in, const int* in_sizes, int n_in,
                              void* d_out, int out_size) {
    const float* text     = (const float*)d_in[0];
    const float* label    = (const float*)d_in[1];
    const int*   tgt      = (const int*)d_in[2];
    const float* curv_log = (const float*)d_in[3];
    const float* ta_log   = (const float*)d_in[4];
    const float* la_log   = (const float*)d_in[5];
    float* out = (float*)d_out;

    cudaFuncSetAttribute(clloss_main2, cudaFuncAttributeMaxDynamicSharedMemorySize, SMEM_BYTES);

    prep_kernel<<<M_ROWS + C_COLS, 256>>>(text, label, curv_log, ta_log, la_log);
    clloss_main2<<<M_ROWS / BM, NTH, SMEM_BYTES>>>(tgt, curv_log, out);
}

// round 4
// speedup vs baseline: 1.7468x; 1.4757x over previous
#include <cuda_runtime.h>
#include <cuda_bf16.h>
#include <math.h>
#include <stdint.h>

#define M_ROWS 8192
#define C_COLS 4096
#define D_DIM  768

#define BM 128
#define BN 128
#define BK 32
#define NTH 256
#define NKC (D_DIM / BK)          // 24
#define NMT (M_ROWS / BM)         // 64
#define NCT (C_COLS / BN)         // 32

#define LD   (BK + 8)             // 40 elems, 80B row stride (conflict-free ldmatrix)
#define TILE_ELEMS (BM * LD)      // 5120
#define TILE_BYTES (TILE_ELEMS * 2)        // 10240
#define STAGE_BYTES (2 * TILE_BYTES)       // 20480 (A then B)
#define NSTAGE 4
#define RED_OFF (NSTAGE * STAGE_BYTES)     // 81920
#define SMEM_BYTES (RED_OFF + 2 * 3 * BM * 4)  // + r1/r2/rp[2][128] = 85 KB

__device__ __align__(16) __nv_bfloat16 g_A[M_ROWS * D_DIM];
__device__ __align__(16) __nv_bfloat16 g_B[C_COLS * D_DIM];
__device__ float g_at[M_ROWS];
__device__ float g_bt[C_COLS];
__device__ float g_p1[NCT * M_ROWS], g_p2[NCT * M_ROWS], g_pp[NCT * M_ROWS];

__device__ __forceinline__ uint32_t smem_u32(const void* p) {
    uint32_t a;
    asm("{ .reg .u64 t; cvta.to.shared.u64 t, %1; cvt.u32.u64 %0, t; }" : "=r"(a) : "l"(p));
    return a;
}
__device__ __forceinline__ void cp16(uint32_t dst, const void* src) {
    asm volatile("cp.async.cg.shared.global [%0], [%1], 16;" :: "r"(dst), "l"(src));
}
__device__ __forceinline__ void cp_commit() { asm volatile("cp.async.commit_group;"); }
template<int N> __device__ __forceinline__ void cp_wait() {
    asm volatile("cp.async.wait_group %0;" :: "n"(N));
}
__device__ __forceinline__ void ldsm4(uint32_t* r, uint32_t addr) {
    asm volatile("ldmatrix.sync.aligned.m8n8.x4.shared.b16 {%0,%1,%2,%3}, [%4];"
                 : "=r"(r[0]), "=r"(r[1]), "=r"(r[2]), "=r"(r[3]) : "r"(addr));
}
__device__ __forceinline__ void mma16816(float* c, const uint32_t* a, uint32_t b0, uint32_t b1) {
    asm volatile(
        "mma.sync.aligned.m16n8k16.row.col.f32.bf16.bf16.f32 "
        "{%0,%1,%2,%3}, {%4,%5,%6,%7}, {%8,%9}, {%0,%1,%2,%3};\n"
        : "+f"(c[0]), "+f"(c[1]), "+f"(c[2]), "+f"(c[3])
        : "r"(a[0]), "r"(a[1]), "r"(a[2]), "r"(a[3]), "r"(b0), "r"(b1));
}

// ---------------------------------------------------------------------------
// Prep: scale -> exp_map0 -> bf16 space comps + fp32 time. One block per row.
// ---------------------------------------------------------------------------
__global__ void prep_kernel(const float* __restrict__ text,
                            const float* __restrict__ label,
                            const float* __restrict__ curv_log,
                            const float* __restrict__ ta_log,
                            const float* __restrict__ la_log) {
    const int which = blockIdx.x >= M_ROWS;
    const int row = which ? blockIdx.x - M_ROWS : blockIdx.x;
    const int tid = threadIdx.x;
    const float alpha = expf(which ? la_log[0] : ta_log[0]);
    const float curv  = expf(curv_log[0]);
    const float* xr = (which ? label : text) + (size_t)row * D_DIM;

    float v0 = xr[tid      ] * alpha;
    float v1 = xr[tid + 256] * alpha;
    float v2 = xr[tid + 512] * alpha;
    float ss = v0 * v0 + v1 * v1 + v2 * v2;
    #pragma unroll
    for (int o = 16; o > 0; o >>= 1) ss += __shfl_xor_sync(0xffffffffu, ss, o);
    __shared__ float ws[8];
    if ((tid & 31) == 0) ws[tid >> 5] = ss;
    __syncthreads();
    const float sumsq = ws[0]+ws[1]+ws[2]+ws[3]+ws[4]+ws[5]+ws[6]+ws[7];

    const float rc = sqrtf(curv) * sqrtf(sumsq);
    const float sf = sinhf(rc) / fmaxf(rc, 1e-8f);

    __nv_bfloat16* out = which ? g_B : g_A;
    out[(size_t)row * D_DIM + tid      ] = __float2bfloat16(sf * v0);
    out[(size_t)row * D_DIM + tid + 256] = __float2bfloat16(sf * v1);
    out[(size_t)row * D_DIM + tid + 512] = __float2bfloat16(sf * v2);
    if (tid == 0)
        (which ? g_bt : g_at)[row] = sqrtf(1.0f / curv + sf * sf * sumsq);
}

// ---------------------------------------------------------------------------
// Stage loader: A[128x32] + B[128x32] bf16 into ring slot. 1024 cp16 / 256 thr.
// ---------------------------------------------------------------------------
__device__ __forceinline__ void load_stage(char* smem, int slot, int mt, int ct,
                                           int kc, int tid) {
    char* sb = smem + slot * STAGE_BYTES;
    const __nv_bfloat16* Ag = g_A + ((size_t)mt * BM) * D_DIM + kc * BK;
    const __nv_bfloat16* Bg = g_B + ((size_t)ct * BN) * D_DIM + kc * BK;
    #pragma unroll
    for (int t = 0; t < 2; ++t) {
        int i = tid + t * NTH;
        int r = i >> 2, ch = (i & 3) * 8;
        cp16(smem_u32(sb + (r * LD + ch) * 2), Ag + (size_t)r * D_DIM + ch);
        cp16(smem_u32(sb + TILE_BYTES + (r * LD + ch) * 2), Bg + (size_t)r * D_DIM + ch);
    }
}

// ---------------------------------------------------------------------------
// Main GEMM: grid = 64 mt x 32 ct = 2048 CTAs, 256 thr, 2 CTAs/SM.
// Warp tile 32x64. 4-stage cp.async ring, prefetch distance 3.
// Epilogue: per-row top-2 of v = xt*yt - dot within this 128x128 tile,
// partials to global, merged by merge_loss.
// ---------------------------------------------------------------------------
__global__ void __launch_bounds__(NTH, 2)
clloss_main(const int* __restrict__ target) {
    extern __shared__ char smem[];
    const int tid  = threadIdx.x;
    const int warp = tid >> 5;
    const int lane = tid & 31;
    const int g    = lane >> 2;
    const int q    = lane & 3;
    const int wm   = warp >> 1;     // 0..3
    const int wn   = warp & 1;      // 0..1
    const int ct   = blockIdx.x & (NCT - 1);
    const int mt   = blockIdx.x >> 5;

    // Prologue: prefetch stages 0..2
    load_stage(smem, 0, mt, ct, 0, tid); cp_commit();
    load_stage(smem, 1, mt, ct, 1, tid); cp_commit();
    load_stage(smem, 2, mt, ct, 2, tid); cp_commit();

    // ldmatrix lane addressing (byte offsets within a stage slot)
    const uint32_t s0 = smem_u32(smem);
    const uint32_t aOff = (uint32_t)(((wm * 32 + (lane & 15)) * LD + (lane >> 4) * 8) * 2);
    const int bn = (lane & 7) + ((lane & 16) >> 1);
    const uint32_t bOff = (uint32_t)TILE_BYTES +
                          (uint32_t)(((wn * 64 + bn) * LD + ((lane >> 3) & 1) * 8) * 2);

    float acc[2][8][4];
    #pragma unroll
    for (int mi = 0; mi < 2; ++mi)
        #pragma unroll
        for (int ni = 0; ni < 8; ++ni)
            #pragma unroll
            for (int r = 0; r < 4; ++r) acc[mi][ni][r] = 0.0f;

    for (int kc = 0; kc < NKC; ++kc) {
        if (kc <= NKC - 3)      cp_wait<2>();
        else if (kc == NKC - 2) cp_wait<1>();
        else                    cp_wait<0>();
        __syncthreads();
        if (kc + 3 < NKC) {
            load_stage(smem, (kc + 3) & 3, mt, ct, kc + 3, tid);
            cp_commit();
        }
        const uint32_t sb = s0 + (uint32_t)((kc & 3) * STAGE_BYTES);
        #pragma unroll
        for (int ks = 0; ks < 2; ++ks) {
            uint32_t a[2][4], b[4][4];
            ldsm4(a[0], sb + aOff + ks * 32);
            ldsm4(a[1], sb + aOff + ks * 32 + 16 * LD * 2);
            #pragma unroll
            for (int nb = 0; nb < 4; ++nb)
                ldsm4(b[nb], sb + bOff + ks * 32 + nb * 16 * LD * 2);
            #pragma unroll
            for (int mi = 0; mi < 2; ++mi)
                #pragma unroll
                for (int ni = 0; ni < 8; ++ni)
                    mma16816(acc[mi][ni], a[mi],
                             b[ni >> 1][(ni & 1) * 2], b[ni >> 1][(ni & 1) * 2 + 1]);
        }
        __syncthreads();
    }

    // Epilogue: track per-row top-2 + positive over this tile's 128 cols.
    float xt[4]; int tg[4];
    #pragma unroll
    for (int i = 0; i < 4; ++i) {
        const int rg = mt * BM + wm * 32 + (i >> 1) * 16 + (i & 1) * 8 + g;
        xt[i] = g_at[rg];
        tg[i] = target[rg];
    }
    const float FINF = __int_as_float(0x7f800000);
    float m1[4], m2[4], vp[4];
    #pragma unroll
    for (int i = 0; i < 4; ++i) { m1[i] = FINF; m2[i] = FINF; vp[i] = FINF; }

    #pragma unroll
    for (int ni = 0; ni < 8; ++ni) {
        const int cg  = ct * BN + wn * 64 + ni * 8 + 2 * q;
        const float yt0 = g_bt[cg];
        const float yt1 = g_bt[cg + 1];
        #pragma unroll
        for (int mi = 0; mi < 2; ++mi) {
            #pragma unroll
            for (int h = 0; h < 2; ++h) {
                const int i = mi * 2 + h;
                const float va = fmaf(xt[i], yt0, -acc[mi][ni][h * 2 + 0]);
                const float vb = fmaf(xt[i], yt1, -acc[mi][ni][h * 2 + 1]);
                if (cg == tg[i]) vp[i] = va;
                else if (va < m1[i]) { m2[i] = m1[i]; m1[i] = va; }
                else if (va < m2[i]) m2[i] = va;
                if (cg + 1 == tg[i]) vp[i] = vb;
                else if (vb < m1[i]) { m2[i] = m1[i]; m1[i] = vb; }
                else if (vb < m2[i]) m2[i] = vb;
            }
        }
    }

    // Quad merge (q lanes share rows, cover different cols)
    #pragma unroll
    for (int i = 0; i < 4; ++i) {
        #pragma unroll
        for (int off = 1; off <= 2; off <<= 1) {
            float o1 = __shfl_xor_sync(0xffffffffu, m1[i], off);
            float o2 = __shfl_xor_sync(0xffffffffu, m2[i], off);
            float op = __shfl_xor_sync(0xffffffffu, vp[i], off);
            float n1 = fminf(m1[i], o1);
            float n2 = fminf(fmaxf(m1[i], o1), fminf(m2[i], o2));
            m1[i] = n1; m2[i] = n2;
            vp[i] = fminf(vp[i], op);
        }
    }

    // wn merge via smem, then write partials for this (row, ct)
    float* r1 = (float*)(smem + RED_OFF);
    float* r2 = r1 + 2 * BM;
    float* rp = r2 + 2 * BM;
    if (q == 0) {
        #pragma unroll
        for (int i = 0; i < 4; ++i) {
            const int rl = wm * 32 + (i >> 1) * 16 + (i & 1) * 8 + g;
            r1[wn * BM + rl] = m1[i];
            r2[wn * BM + rl] = m2[i];
            rp[wn * BM + rl] = vp[i];
        }
    }
    __syncthreads();
    if (tid < BM) {
        const float a1 = r1[tid], b1 = r1[BM + tid];
        const float a2 = r2[tid], b2 = r2[BM + tid];
        const float n1 = fminf(a1, b1);
        const float n2 = fminf(fmaxf(a1, b1), fminf(a2, b2));
        const int gi = ct * M_ROWS + mt * BM + tid;
        g_p1[gi] = n1;
        g_p2[gi] = n2;
        g_pp[gi] = fminf(rp[tid], rp[BM + tid]);
    }
}

// ---------------------------------------------------------------------------
// Merge partials across 32 ct-tiles + compute per-sample loss.
// ---------------------------------------------------------------------------
__global__ void merge_loss(const float* __restrict__ curv_log, float* __restrict__ out) {
    const int r = blockIdx.x * 256 + threadIdx.x;
    float a1 = g_p1[r], a2 = g_p2[r], ap = g_pp[r];
    #pragma unroll 4
    for (int ct = 1; ct < NCT; ++ct) {
        const float b1 = g_p1[ct * M_ROWS + r];
        const float b2 = g_p2[ct * M_ROWS + r];
        const float n1 = fminf(a1, b1);
        a2 = fminf(fmaxf(a1, b1), fminf(a2, b2));
        a1 = n1;
        ap = fminf(ap, g_pp[ct * M_ROWS + r]);
    }
    const float curv = expf(curv_log[0]);
    const float sc = sqrtf(curv);
    const float dp = acoshf(fmaxf(curv * ap, 1.0f)) / sc;
    const float d1 = acoshf(fmaxf(curv * a1, 1.0f)) / sc;
    const float d2 = acoshf(fmaxf(curv * a2, 1.0f)) / sc;
    const float s0 = -dp, s1 = -d1, s2 = -d2;
    const float mx = fmaxf(s0, fmaxf(s1, s2));
    out[r] = mx + logf(expf(s0 - mx) + expf(s1 - mx) + expf(s2 - mx)) - s0;
}

extern "C" void kernel_launch(void* const* d_in, const int* in_sizes, int n_in,
                              void* d_out, int out_size) {
    const float* text     = (const float*)d_in[0];
    const float* label    = (const float*)d_in[1];
    const int*   tgt      = (const int*)d_in[2];
    const float* curv_log = (const float*)d_in[3];
    const float* ta_log   = (const float*)d_in[4];
    const float* la_log   = (const float*)d_in[5];
    float* out = (float*)d_out;

    cudaFuncSetAttribute(clloss_main, cudaFuncAttributeMaxDynamicSharedMemorySize, SMEM_BYTES);

    prep_kernel<<<M_ROWS + C_COLS, 256>>>(text, label, curv_log, ta_log, la_log);
    clloss_main<<<NMT * NCT, NTH, SMEM_BYTES>>>(tgt);
    merge_loss<<<M_ROWS / 256, 256>>>(curv_log, out);
}

// round 5
// speedup vs baseline: 2.0669x; 1.1833x over previous
#include <cuda_runtime.h>
#include <cuda_bf16.h>
#include <math.h>
#include <stdint.h>

#define M_ROWS 8192
#define C_COLS 4096
#define D_DIM  768

#define BM 128
#define BN 128
#define BK 64
#define NTH 256
#define NKC (D_DIM / BK)          // 12
#define NMT (M_ROWS / BM)         // 64
#define NCT (C_COLS / BN)         // 32

#define LD   (BK + 8)             // 72 elems, 144B row stride (conflict-free ldmatrix)
#define TILE_BYTES (BM * LD * 2)           // 18432
#define STAGE_BYTES (2 * TILE_BYTES)       // 36864 (A then B)
#define NSTAGE 3
#define SMEM_BYTES (NSTAGE * STAGE_BYTES)  // 110592 (reduction reuses stage 0)

__device__ __align__(16) __nv_bfloat16 g_A[M_ROWS * D_DIM];
__device__ __align__(16) __nv_bfloat16 g_B[C_COLS * D_DIM];
__device__ float g_at[M_ROWS];
__device__ float g_bt[C_COLS];
__device__ float g_p1[NCT * M_ROWS], g_p2[NCT * M_ROWS], g_pp[NCT * M_ROWS];

__device__ __forceinline__ uint32_t smem_u32(const void* p) {
    uint32_t a;
    asm("{ .reg .u64 t; cvta.to.shared.u64 t, %1; cvt.u32.u64 %0, t; }" : "=r"(a) : "l"(p));
    return a;
}
__device__ __forceinline__ void cp16(uint32_t dst, const void* src) {
    asm volatile("cp.async.cg.shared.global [%0], [%1], 16;" :: "r"(dst), "l"(src));
}
__device__ __forceinline__ void cp_commit() { asm volatile("cp.async.commit_group;"); }
template<int N> __device__ __forceinline__ void cp_wait() {
    asm volatile("cp.async.wait_group %0;" :: "n"(N));
}
__device__ __forceinline__ void ldsm4(uint32_t* r, uint32_t addr) {
    asm volatile("ldmatrix.sync.aligned.m8n8.x4.shared.b16 {%0,%1,%2,%3}, [%4];"
                 : "=r"(r[0]), "=r"(r[1]), "=r"(r[2]), "=r"(r[3]) : "r"(addr));
}
__device__ __forceinline__ void mma16816(float* c, const uint32_t* a, uint32_t b0, uint32_t b1) {
    asm volatile(
        "mma.sync.aligned.m16n8k16.row.col.f32.bf16.bf16.f32 "
        "{%0,%1,%2,%3}, {%4,%5,%6,%7}, {%8,%9}, {%0,%1,%2,%3};\n"
        : "+f"(c[0]), "+f"(c[1]), "+f"(c[2]), "+f"(c[3])
        : "r"(a[0]), "r"(a[1]), "r"(a[2]), "r"(a[3]), "r"(b0), "r"(b1));
}

// ---------------------------------------------------------------------------
// Prep: warp-per-row. 8 rows per 256-thread block; float4 loads; warp-reduce
// only (no block barrier). rows [0,8192)=text, [8192,12288)=labels.
// ---------------------------------------------------------------------------
__global__ void __launch_bounds__(256)
prep_kernel(const float* __restrict__ text,
            const float* __restrict__ label,
            const float* __restrict__ curv_log,
            const float* __restrict__ ta_log,
            const float* __restrict__ la_log) {
    const int gw = blockIdx.x * 8 + (threadIdx.x >> 5);
    const int lane = threadIdx.x & 31;
    const int which = gw >= M_ROWS;
    const int row = which ? gw - M_ROWS : gw;
    const float alpha = expf(which ? la_log[0] : ta_log[0]);
    const float curv  = expf(curv_log[0]);
    const float4* xr = (const float4*)((which ? label : text) + (size_t)row * D_DIM);

    float4 v[6];
    float ss = 0.0f;
    #pragma unroll
    for (int j = 0; j < 6; ++j) {
        float4 t = xr[j * 32 + lane];
        t.x *= alpha; t.y *= alpha; t.z *= alpha; t.w *= alpha;
        ss += t.x * t.x + t.y * t.y + t.z * t.z + t.w * t.w;
        v[j] = t;
    }
    #pragma unroll
    for (int o = 16; o > 0; o >>= 1) ss += __shfl_xor_sync(0xffffffffu, ss, o);

    const float rc = sqrtf(curv) * sqrtf(ss);
    const float sf = sinhf(rc) / fmaxf(rc, 1e-8f);

    __nv_bfloat162* o2 = (__nv_bfloat162*)((which ? g_B : g_A) + (size_t)row * D_DIM);
    #pragma unroll
    for (int j = 0; j < 6; ++j) {
        const int e = j * 32 + lane;
        o2[e * 2 + 0] = __nv_bfloat162(__float2bfloat16(sf * v[j].x), __float2bfloat16(sf * v[j].y));
        o2[e * 2 + 1] = __nv_bfloat162(__float2bfloat16(sf * v[j].z), __float2bfloat16(sf * v[j].w));
    }
    if (lane == 0)
        (which ? g_bt : g_at)[row] = sqrtf(1.0f / curv + sf * sf * ss);
}

// ---------------------------------------------------------------------------
// Stage loader: A[128x64] + B[128x64] bf16 into ring slot. 2048 cp16 / 256 thr.
// ---------------------------------------------------------------------------
__device__ __forceinline__ void load_stage(char* smem, int slot, int mt, int ct,
                                           int kc, int tid) {
    char* sb = smem + slot * STAGE_BYTES;
    const __nv_bfloat16* Ag = g_A + ((size_t)mt * BM) * D_DIM + kc * BK;
    const __nv_bfloat16* Bg = g_B + ((size_t)ct * BN) * D_DIM + kc * BK;
    #pragma unroll
    for (int t = 0; t < 4; ++t) {
        int i = tid + t * NTH;          // 0..1023
        int r = i >> 3, ch = (i & 7) * 8;
        cp16(smem_u32(sb + (r * LD + ch) * 2), Ag + (size_t)r * D_DIM + ch);
        cp16(smem_u32(sb + TILE_BYTES + (r * LD + ch) * 2), Bg + (size_t)r * D_DIM + ch);
    }
}

// ---------------------------------------------------------------------------
// Main GEMM: grid = 64 mt x 32 ct = 2048 CTAs, 256 thr, 2 CTAs/SM.
// Warp tile 32x64; 3-stage ring, distance-2 prefetch, ONE barrier per chunk.
// ---------------------------------------------------------------------------
__global__ void __launch_bounds__(NTH, 2)
clloss_main(const int* __restrict__ target) {
    extern __shared__ char smem[];
    const int tid  = threadIdx.x;
    const int warp = tid >> 5;
    const int lane = tid & 31;
    const int g    = lane >> 2;
    const int q    = lane & 3;
    const int wm   = warp >> 1;     // 0..3
    const int wn   = warp & 1;      // 0..1
    const int ct   = blockIdx.x & (NCT - 1);
    const int mt   = blockIdx.x >> 5;

    load_stage(smem, 0, mt, ct, 0, tid); cp_commit();
    load_stage(smem, 1, mt, ct, 1, tid); cp_commit();

    const uint32_t s0 = smem_u32(smem);
    const uint32_t aOff = (uint32_t)(((wm * 32 + (lane & 15)) * LD + (lane >> 4) * 8) * 2);
    const int bn = (lane & 7) + ((lane & 16) >> 1);
    const uint32_t bOff = (uint32_t)TILE_BYTES +
                          (uint32_t)(((wn * 64 + bn) * LD + ((lane >> 3) & 1) * 8) * 2);

    float acc[2][8][4];
    #pragma unroll
    for (int mi = 0; mi < 2; ++mi)
        #pragma unroll
        for (int ni = 0; ni < 8; ++ni)
            #pragma unroll
            for (int r = 0; r < 4; ++r) acc[mi][ni][r] = 0.0f;

    #pragma unroll 1
    for (int kc = 0; kc < NKC; ++kc) {
        if (kc < NKC - 1) cp_wait<1>(); else cp_wait<0>();
        __syncthreads();               // single barrier: stage kc ready, slot (kc+2)%3 free
        if (kc + 2 < NKC) {
            load_stage(smem, (kc + 2) % 3, mt, ct, kc + 2, tid);
            cp_commit();
        }
        const uint32_t sb = s0 + (uint32_t)((kc % 3) * STAGE_BYTES);
        #pragma unroll
        for (int ks = 0; ks < 4; ++ks) {
            uint32_t a[2][4], b[4][4];
            ldsm4(a[0], sb + aOff + ks * 32);
            ldsm4(a[1], sb + aOff + ks * 32 + 16 * LD * 2);
            #pragma unroll
            for (int nb = 0; nb < 4; ++nb)
                ldsm4(b[nb], sb + bOff + ks * 32 + nb * 16 * LD * 2);
            #pragma unroll
            for (int mi = 0; mi < 2; ++mi)
                #pragma unroll
                for (int ni = 0; ni < 8; ++ni)
                    mma16816(acc[mi][ni], a[mi],
                             b[ni >> 1][(ni & 1) * 2], b[ni >> 1][(ni & 1) * 2 + 1]);
        }
    }

    // Epilogue: per-row top-2 + positive over this tile (v = xt*yt - dot).
    float xt[4]; int tg[4];
    #pragma unroll
    for (int i = 0; i < 4; ++i) {
        const int rg = mt * BM + wm * 32 + (i >> 1) * 16 + (i & 1) * 8 + g;
        xt[i] = g_at[rg];
        tg[i] = target[rg];
    }
    const float FINF = __int_as_float(0x7f800000);
    float m1[4], m2[4], vp[4];
    #pragma unroll
    for (int i = 0; i < 4; ++i) { m1[i] = FINF; m2[i] = FINF; vp[i] = FINF; }

    #pragma unroll
    for (int ni = 0; ni < 8; ++ni) {
        const int cg  = ct * BN + wn * 64 + ni * 8 + 2 * q;
        const float yt0 = g_bt[cg];
        const float yt1 = g_bt[cg + 1];
        #pragma unroll
        for (int mi = 0; mi < 2; ++mi) {
            #pragma unroll
            for (int h = 0; h < 2; ++h) {
                const int i = mi * 2 + h;
                const float va = fmaf(xt[i], yt0, -acc[mi][ni][h * 2 + 0]);
                const float vb = fmaf(xt[i], yt1, -acc[mi][ni][h * 2 + 1]);
                if (cg == tg[i]) vp[i] = va;
                else if (va < m1[i]) { m2[i] = m1[i]; m1[i] = va; }
                else if (va < m2[i]) m2[i] = va;
                if (cg + 1 == tg[i]) vp[i] = vb;
                else if (vb < m1[i]) { m2[i] = m1[i]; m1[i] = vb; }
                else if (vb < m2[i]) m2[i] = vb;
            }
        }
    }

    // Quad merge (q lanes share rows)
    #pragma unroll
    for (int i = 0; i < 4; ++i) {
        #pragma unroll
        for (int off = 1; off <= 2; off <<= 1) {
            float o1 = __shfl_xor_sync(0xffffffffu, m1[i], off);
            float o2 = __shfl_xor_sync(0xffffffffu, m2[i], off);
            float op = __shfl_xor_sync(0xffffffffu, vp[i], off);
            float n1 = fminf(m1[i], o1);
            float n2 = fminf(fmaxf(m1[i], o1), fminf(m2[i], o2));
            m1[i] = n1; m2[i] = n2;
            vp[i] = fminf(vp[i], op);
        }
    }

    // wn merge via smem (reuses stage 0 region — safe: slot 0 last read at kc=9,
    // protected by the kc=11 top barrier), then write partials.
    float* r1 = (float*)smem;
    float* r2 = r1 + 2 * BM;
    float* rp = r2 + 2 * BM;
    if (q == 0) {
        #pragma unroll
        for (int i = 0; i < 4; ++i) {
            const int rl = wm * 32 + (i >> 1) * 16 + (i & 1) * 8 + g;
            r1[wn * BM + rl] = m1[i];
            r2[wn * BM + rl] = m2[i];
            rp[wn * BM + rl] = vp[i];
        }
    }
    __syncthreads();
    if (tid < BM) {
        const float a1 = r1[tid], b1 = r1[BM + tid];
        const float a2 = r2[tid], b2 = r2[BM + tid];
        const float n1 = fminf(a1, b1);
        const float n2 = fminf(fmaxf(a1, b1), fminf(a2, b2));
        const int gi = ct * M_ROWS + mt * BM + tid;
        g_p1[gi] = n1;
        g_p2[gi] = n2;
        g_pp[gi] = fminf(rp[tid], rp[BM + tid]);
    }
}

// ---------------------------------------------------------------------------
// Merge partials across 32 ct-tiles + per-sample loss.
// ---------------------------------------------------------------------------
__global__ void merge_loss(const float* __restrict__ curv_log, float* __restrict__ out) {
    const int r = blockIdx.x * 256 + threadIdx.x;
    float a1 = g_p1[r], a2 = g_p2[r], ap = g_pp[r];
    #pragma unroll 4
    for (int ct = 1; ct < NCT; ++ct) {
        const float b1 = g_p1[ct * M_ROWS + r];
        const float b2 = g_p2[ct * M_ROWS + r];
        const float n1 = fminf(a1, b1);
        a2 = fminf(fmaxf(a1, b1), fminf(a2, b2));
        a1 = n1;
        ap = fminf(ap, g_pp[ct * M_ROWS + r]);
    }
    const float curv = expf(curv_log[0]);
    const float sc = sqrtf(curv);
    const float dp = acoshf(fmaxf(curv * ap, 1.0f)) / sc;
    const float d1 = acoshf(fmaxf(curv * a1, 1.0f)) / sc;
    const float d2 = acoshf(fmaxf(curv * a2, 1.0f)) / sc;
    const float s0 = -dp, s1 = -d1, s2 = -d2;
    const float mx = fmaxf(s0, fmaxf(s1, s2));
    out[r] = mx + logf(expf(s0 - mx) + expf(s1 - mx) + expf(s2 - mx)) - s0;
}

extern "C" void kernel_launch(void* const* d_in, const int* in_sizes, int n_in,
                              void* d_out, int out_size) {
    const float* text     = (const float*)d_in[0];
    const float* label    = (const float*)d_in[1];
    const int*   tgt      = (const int*)d_in[2];
    const float* curv_log = (const float*)d_in[3];
    const float* ta_log   = (const float*)d_in[4];
    const float* la_log   = (const float*)d_in[5];
    float* out = (float*)d_out;

    cudaFuncSetAttribute(clloss_main, cudaFuncAttributeMaxDynamicSharedMemorySize, SMEM_BYTES);

    prep_kernel<<<(M_ROWS + C_COLS) / 8, 256>>>(text, label, curv_log, ta_log, la_log);
    clloss_main<<<NMT * NCT, NTH, SMEM_BYTES>>>(tgt);
    merge_loss<<<M_ROWS / 256, 256>>>(curv_log, out);
}